// round 13
// baseline (speedup 1.0000x reference)
#include <cuda_runtime.h>
#include <cstdint>

#define SIGMA 0.1f
#define BANDS 256
#define KSEL  64
#define B_DIM 128
#define F4_PER_TILE 256              // 1024 floats / 4
#define TOTAL_TILES (B_DIM * KSEL)   // 8192
#define GRID_BLOCKS 1184             // 148 SMs * 8 blocks -> one resident wave

// ---------------------------------------------------------------------------
// Fused kernel: every block (256 threads) recomputes the gate + top-k
// selection locally in smem (cheap, fully parallel across blocks — replaces a
// serial select kernel + PDL handoff), then grid-strides over (b,j) tiles
// doing the BW-bound gather+scale with a 2-deep load pipeline.
// ---------------------------------------------------------------------------
__global__ __launch_bounds__(256, 8)
void fused_kernel(const float*  __restrict__ mu,
                  const float*  __restrict__ noise,
                  const float*  __restrict__ extra,
                  const float4* __restrict__ x,
                  float4*       __restrict__ out)
{
    __shared__ float    s_g[BANDS];
    __shared__ unsigned s_bal[BANDS / 32];
    __shared__ int      s_idx [KSEL];
    __shared__ float    s_gate[KSEL];

    const int i    = threadIdx.x;
    const int lane = i & 31;
    const int warp = i >> 5;

    // ---- selection prologue (identical in every block) -------------------
    // gate_i = clip(mu + SIGMA*(noise + 0.25*extra) + 0.5, 0, 1)
    float z = mu[i] + SIGMA * (noise[i] + 0.25f * extra[i]);
    float g = fminf(fmaxf(z + 0.5f, 0.0f), 1.0f);
    s_g[i] = g;
    __syncthreads();

    // rank_i = # bands strictly better (JAX top_k tie-break: lower idx wins)
    int rank = 0;
    const float4* gate4 = reinterpret_cast<const float4*>(s_g);
    #pragma unroll 8
    for (int j4 = 0; j4 < BANDS / 4; j4++) {
        float4 gv = gate4[j4];
        int j = j4 * 4;
        rank += (gv.x > g) || (gv.x == g && (j + 0) < i);
        rank += (gv.y > g) || (gv.y == g && (j + 1) < i);
        rank += (gv.z > g) || (gv.z == g && (j + 2) < i);
        rank += (gv.w > g) || (gv.w == g && (j + 3) < i);
    }

    bool     sel = (rank < KSEL);
    unsigned bal = __ballot_sync(0xffffffffu, sel);
    if (lane == 0) s_bal[warp] = bal;
    __syncthreads();

    if (sel) {
        // slot = # selected bands with smaller index => ascending-sorted idx
        int pos = __popc(bal & ((1u << lane) - 1u));
        #pragma unroll
        for (int w = 0; w < BANDS / 32; w++)
            pos += (w < warp) ? __popc(s_bal[w]) : 0;
        s_idx [pos] = i;
        s_gate[pos] = g;
    }
    __syncthreads();

    // ---- gather + scale (BW-bound part) ----------------------------------
    const int t      = threadIdx.x;
    const int stride = gridDim.x;
    int bj           = blockIdx.x;

    // prologue load
    int    j  = bj & (KSEL - 1);
    int    b  = bj >> 6;
    float4 v  = x[(size_t)(b * BANDS + s_idx[j]) * F4_PER_TILE + t];
    float  gv = s_gate[j];

    for (int nbj = bj + stride; nbj < TOTAL_TILES; nbj += stride) {
        // issue next tile's load before storing current
        int    nj  = nbj & (KSEL - 1);
        int    nb  = nbj >> 6;
        float4 nv  = x[(size_t)(nb * BANDS + s_idx[nj]) * F4_PER_TILE + t];
        float  ngv = s_gate[nj];

        v.x *= gv; v.y *= gv; v.z *= gv; v.w *= gv;
        out[(size_t)bj * F4_PER_TILE + t] = v;

        v = nv; gv = ngv; bj = nbj;
    }

    v.x *= gv; v.y *= gv; v.z *= gv; v.w *= gv;
    out[(size_t)bj * F4_PER_TILE + t] = v;
}

extern "C" void kernel_launch(void* const* d_in, const int* in_sizes, int n_in,
                              void* d_out, int out_size)
{
    const float* x     = (const float*)d_in[0];   // (128,1,256,32,32)
    const float* mu    = (const float*)d_in[1];   // (256,)
    const float* noise = (const float*)d_in[2];   // (256,)
    const float* extra = (const float*)d_in[3];   // (256,)
    (void)in_sizes; (void)n_in; (void)out_size;

    fused_kernel<<<GRID_BLOCKS, 256>>>(mu, noise, extra,
                                       (const float4*)x, (float4*)d_out);
}